// round 13
// baseline (speedup 1.0000x reference)
#include <cuda_runtime.h>

// Batched Viterbi decode: B=1024 sequences, T=1024 steps, K=48 tags.
// Output layout (float32): [0, B) = path scores, [B, B + B*T) = best paths.
//
// R11: forward pass computes VALUES ONLY (FMNMX chains, no argmax tracking ->
// ~2.5x fewer alu ops) and stores the entering forward-variable rows (192MB).
// Backpointers are recomputed only along the optimal path by a warp-per-seq
// chase using an exact ordered-int warp argmax (REDUX + ballot + ffs).

namespace {
constexpr int Bn = 1024;
constexpr int Tn = 1024;
constexpr int Kn = 48;
constexpr int START_TAG = 46;
constexpr float NEGV = -10000.0f;

constexpr int SUBS = 2;              // sequences per forward block
constexpr int NTHREADS = SUBS * Kn;  // 96 threads
}

// Scratch (__device__ globals: allowed; no allocation APIs).
__device__ __align__(16) float g_fv[(size_t)Bn * Tn * Kn];  // 192 MB fv rows
__device__ int g_btag[Bn];                                   // terminal best tag

// packed f32x2 add: two independent IEEE-rn adds in one instruction
__device__ __forceinline__ void fadd2(unsigned long long a, unsigned long long b,
                                      float& lo, float& hi) {
    unsigned long long s;
    asm("add.rn.f32x2 %0, %1, %2;" : "=l"(s) : "l"(a), "l"(b));
    asm("mov.b64 {%0, %1}, %2;" : "=f"(lo), "=f"(hi) : "l"(s));
}

// monotone bijection float -> u32 (order-preserving for all finite floats)
__device__ __forceinline__ unsigned ordered_u32(float x) {
    int b = __float_as_int(x);
    return (unsigned)(b ^ ((b >> 31) | 0x80000000));
}

__global__ __launch_bounds__(NTHREADS) void viterbi_fwd(
    const float* __restrict__ feats,   // [B, T, K]
    const float* __restrict__ trans,   // [K, K]  trans[next][prev]
    float* __restrict__ out)           // [B] scores (paths filled by path kernel)
{
    __shared__ __align__(16) float fvbuf[2][SUBS][Kn];

    const int tid = threadIdx.x;
    const int sub = tid / Kn;
    const int j   = tid - sub * Kn;    // next-tag owned by this thread
    const int b   = blockIdx.x * SUBS + sub;

    // Transition row for my next-tag, packed into f32x2 register pairs.
    unsigned long long tr2[Kn / 2];
#pragma unroll
    for (int p = 0; p < Kn; p += 2) {
        unsigned long long lo = __float_as_uint(trans[j * Kn + p]);
        unsigned long long hi = __float_as_uint(trans[j * Kn + p + 1]);
        tr2[p / 2] = lo | (hi << 32);
    }

    const float init = (j == START_TAG) ? 0.0f : NEGV;
    fvbuf[0][sub][j] = init;

    float* fvout = g_fv + (size_t)b * Tn * Kn;  // rows: fv entering step t
    fvout[j] = init;                             // row t = 0
    __syncthreads();

    const float* fb = feats + (size_t)b * Tn * Kn;

    // depth-2 register pipeline for the emission loads
    float f0 = __ldg(fb + j);
    float f1 = __ldg(fb + Kn + j);

    for (int t = 0; t < Tn; ++t) {
        const int rbuf = t & 1;
        const float feat = f0;
        f0 = f1;
        const int tn = (t + 2 < Tn) ? (t + 2) : (Tn - 1);
        f1 = __ldg(fb + (size_t)tn * Kn + j);

        // pull fv into registers as packed pairs (LDS.128)
        const ulonglong2* fvv =
            reinterpret_cast<const ulonglong2*>(&fvbuf[rbuf][sub][0]);
        unsigned long long fvp[Kn / 2];
#pragma unroll
        for (int i = 0; i < Kn / 4; ++i) {
            ulonglong2 v = fvv[i];
            fvp[2 * i] = v.x; fvp[2 * i + 1] = v.y;
        }

        // value-only max: 4 independent FMNMX chains (exact, associative)
        float s0, s1, s2, s3;
        fadd2(fvp[0], tr2[0], s0, s1);
        fadd2(fvp[1], tr2[1], s2, s3);
        float bv0 = s0, bv1 = s1, bv2 = s2, bv3 = s3;
#pragma unroll
        for (int g = 1; g < Kn / 4; ++g) {
            fadd2(fvp[2 * g],     tr2[2 * g],     s0, s1);
            fadd2(fvp[2 * g + 1], tr2[2 * g + 1], s2, s3);
            bv0 = fmaxf(bv0, s0);
            bv1 = fmaxf(bv1, s1);
            bv2 = fmaxf(bv2, s2);
            bv3 = fmaxf(bv3, s3);
        }
        const float bestv = fmaxf(fmaxf(bv0, bv1), fmaxf(bv2, bv3));
        const float nv = bestv + feat;

        fvbuf[rbuf ^ 1][sub][j] = nv;
        if (t + 1 < Tn) fvout[(size_t)(t + 1) * Kn + j] = nv;  // fv entering t+1
        __syncthreads();
    }

    // terminal: strict-> ascending scan reproduces jnp.argmax first-index
    if (j == Kn - 1) {
        const float* fvf = &fvbuf[0][sub][0];  // last write went to buffer 0
        float bestv = fvf[0] + __ldg(trans + (Kn - 1) * Kn);
        int best = 0;
#pragma unroll
        for (int k = 1; k < Kn; ++k) {
            float s = fvf[k] + __ldg(trans + (Kn - 1) * Kn + k);
            if (s > bestv) { bestv = s; best = k; }
        }
        out[b] = bestv;
        g_btag[b] = best;
    }
}

// ---- Path chase: one warp per sequence, argmax recomputed along the path ----
__global__ __launch_bounds__(128) void viterbi_path(
    const float* __restrict__ trans,
    float* __restrict__ out)
{
    const int seq  = blockIdx.x * 4 + (threadIdx.x >> 5);
    const int lane = threadIdx.x & 31;

    const float* fvb = g_fv + (size_t)seq * Tn * Kn;
    float* op = out + Bn + (size_t)seq * Tn;
    int tag = g_btag[seq];

    const int p2 = lane + 32;
    const bool has2 = (p2 < Kn);

    constexpr int PF = 12;  // row prefetch distance
    // warm up: prefetch the last PF rows (192B each, may span 3 lines)
    if (lane < PF) {
        const char* p = (const char*)(fvb + (size_t)(Tn - 1 - lane) * Kn);
        asm volatile("prefetch.global.L1 [%0];" :: "l"(p));
        asm volatile("prefetch.global.L1 [%0];" :: "l"(p + 96));
        asm volatile("prefetch.global.L1 [%0];" :: "l"(p + 191));
    }

    float path_val = 0.0f;
    for (int t = Tn - 1; t >= 0; --t) {
        if (lane == (t & 31)) path_val = (float)tag;  // capture path[t]

        // bptr[t][tag] = first-index argmax_p( fv_t[p] + trans[tag][p] )
        const float* row  = fvb + (size_t)t * Kn;
        const float* trow = trans + tag * Kn;

        float s1 = __ldg(row + lane) + __ldg(trow + lane);
        unsigned o1 = ordered_u32(s1);
        unsigned o2 = 0;  // 0 < ordered(any finite float): safe sentinel
        if (has2) o2 = ordered_u32(__ldg(row + p2) + __ldg(trow + p2));

        unsigned m = (o1 > o2) ? o1 : o2;
        unsigned omax = __reduce_max_sync(0xffffffffu, m);
        unsigned b1 = __ballot_sync(0xffffffffu, o1 == omax);
        unsigned b2 = __ballot_sync(0xffffffffu, o2 == omax);
        tag = b1 ? (__ffs(b1) - 1) : (32 + __ffs(b2) - 1);

        // coalesced flush every 32 steps
        if ((t & 31) == 0) op[t + lane] = path_val;

        // keep rows in L1 ahead of the chase
        const int tp = t - PF;
        if (tp >= 0 && lane < 3) {
            const char* p = (const char*)(fvb + (size_t)tp * Kn);
            const char* q = p + (lane == 0 ? 0 : (lane == 1 ? 96 : 191));
            asm volatile("prefetch.global.L1 [%0];" :: "l"(q));
        }
    }
}

extern "C" void kernel_launch(void* const* d_in, const int* in_sizes, int n_in,
                              void* d_out, int out_size) {
    (void)n_in; (void)out_size;
    const float* feats = (const float*)d_in[0];
    const float* trans = (const float*)d_in[1];
    if (in_sizes[0] == Kn * Kn && in_sizes[1] != Kn * Kn) {
        const float* tmp = feats; feats = trans; trans = tmp;
    }
    float* out = (float*)d_out;

    viterbi_fwd<<<Bn / SUBS, NTHREADS>>>(feats, trans, out);
    viterbi_path<<<Bn / 4, 128>>>(trans, out);
}

// round 15
// speedup vs baseline: 1.2502x; 1.2502x over previous
#include <cuda_runtime.h>

// Batched Viterbi decode: B=1024 sequences, T=1024 steps, K=48 tags.
// Output layout (float32): [0, B) = path scores, [B, B + B*T) = best paths.
//
// R13: (a) path chase: fv-row loads moved into a depth-8 REGISTER pipeline
// (guaranteed, unlike prefetch hints) and trans moved to smem -> only a
// 29-cyc LDS remains on the tag-dependent chain; (b) forward max computed
// as a balanced FMNMX tree (depth 6 vs 11) — fmax is exactly associative,
// values bit-identical.

namespace {
constexpr int Bn = 1024;
constexpr int Tn = 1024;
constexpr int Kn = 48;
constexpr int START_TAG = 46;
constexpr float NEGV = -10000.0f;

constexpr int SUBS = 2;              // sequences per forward block
constexpr int NTHREADS = SUBS * Kn;  // 96 threads

constexpr int PD = 8;                // path-kernel row pipeline depth
}

// Scratch (__device__ globals: allowed; no allocation APIs).
__device__ __align__(16) float g_fv[(size_t)Bn * Tn * Kn];  // 192 MB fv rows
__device__ int g_btag[Bn];                                   // terminal best tag

// packed f32x2 add: two independent IEEE-rn adds in one instruction
__device__ __forceinline__ void fadd2(unsigned long long a, unsigned long long b,
                                      float& lo, float& hi) {
    unsigned long long s;
    asm("add.rn.f32x2 %0, %1, %2;" : "=l"(s) : "l"(a), "l"(b));
    asm("mov.b64 {%0, %1}, %2;" : "=f"(lo), "=f"(hi) : "l"(s));
}

// monotone bijection float -> u32 (order-preserving for all non-NaN floats)
__device__ __forceinline__ unsigned ordered_u32(float x) {
    int b = __float_as_int(x);
    return (unsigned)(b ^ ((b >> 31) | 0x80000000));
}

__global__ __launch_bounds__(NTHREADS) void viterbi_fwd(
    const float* __restrict__ feats,   // [B, T, K]
    const float* __restrict__ trans,   // [K, K]  trans[next][prev]
    float* __restrict__ out)           // [B] scores
{
    __shared__ __align__(16) float fvbuf[2][SUBS][Kn];

    const int tid = threadIdx.x;
    const int sub = tid / Kn;
    const int j   = tid - sub * Kn;    // next-tag owned by this thread
    const int b   = blockIdx.x * SUBS + sub;

    // Transition row for my next-tag, packed into f32x2 register pairs.
    unsigned long long tr2[Kn / 2];
#pragma unroll
    for (int p = 0; p < Kn; p += 2) {
        unsigned long long lo = __float_as_uint(trans[j * Kn + p]);
        unsigned long long hi = __float_as_uint(trans[j * Kn + p + 1]);
        tr2[p / 2] = lo | (hi << 32);
    }

    const float init = (j == START_TAG) ? 0.0f : NEGV;
    fvbuf[0][sub][j] = init;

    float* fvout = g_fv + (size_t)b * Tn * Kn;  // rows: fv entering step t
    fvout[j] = init;                             // row 0
    __syncthreads();

    const float* fb = feats + (size_t)b * Tn * Kn;

    // depth-2 register pipeline for the emission loads
    float f0 = __ldg(fb + j);
    float f1 = __ldg(fb + Kn + j);

    for (int t = 0; t < Tn; ++t) {
        const int rbuf = t & 1;
        const float feat = f0;
        f0 = f1;
        const int tn = (t + 2 < Tn) ? (t + 2) : (Tn - 1);
        f1 = __ldg(fb + (size_t)tn * Kn + j);

        // pull fv into registers as packed pairs (LDS.128)
        const ulonglong2* fvv =
            reinterpret_cast<const ulonglong2*>(&fvbuf[rbuf][sub][0]);
        unsigned long long fvp[Kn / 2];
#pragma unroll
        for (int i = 0; i < Kn / 4; ++i) {
            ulonglong2 v = fvv[i];
            fvp[2 * i] = v.x; fvp[2 * i + 1] = v.y;
        }

        // balanced max tree (fmax exactly associative -> bit-identical)
        float m24[24];
#pragma unroll
        for (int g = 0; g < 12; ++g) {
            float x0, x1, x2, x3;
            fadd2(fvp[2 * g],     tr2[2 * g],     x0, x1);
            fadd2(fvp[2 * g + 1], tr2[2 * g + 1], x2, x3);
            m24[2 * g]     = fmaxf(x0, x1);
            m24[2 * g + 1] = fmaxf(x2, x3);
        }
        float m12[12];
#pragma unroll
        for (int i = 0; i < 12; ++i) m12[i] = fmaxf(m24[2 * i], m24[2 * i + 1]);
        float m6[6];
#pragma unroll
        for (int i = 0; i < 6; ++i) m6[i] = fmaxf(m12[2 * i], m12[2 * i + 1]);
        float m3a = fmaxf(m6[0], m6[1]);
        float m3b = fmaxf(m6[2], m6[3]);
        float m3c = fmaxf(m6[4], m6[5]);
        const float bestv = fmaxf(fmaxf(m3a, m3b), m3c);
        const float nv = bestv + feat;

        fvbuf[rbuf ^ 1][sub][j] = nv;
        if (t + 1 < Tn) fvout[(size_t)(t + 1) * Kn + j] = nv;  // fv entering t+1
        __syncthreads();
    }

    // terminal: strict-> ascending scan reproduces jnp.argmax first-index
    if (j == Kn - 1) {
        const float* fvf = &fvbuf[0][sub][0];  // last write went to buffer 0
        float bestv = fvf[0] + __ldg(trans + (Kn - 1) * Kn);
        int best = 0;
#pragma unroll
        for (int k = 1; k < Kn; ++k) {
            float s = fvf[k] + __ldg(trans + (Kn - 1) * Kn + k);
            if (s > bestv) { bestv = s; best = k; }
        }
        out[b] = bestv;
        g_btag[b] = best;
    }
}

// ---- Path chase: one warp per sequence; fv rows in a register pipeline ----
__global__ __launch_bounds__(128) void viterbi_path(
    const float* __restrict__ trans,
    float* __restrict__ out)
{
    __shared__ float s_tr[Kn * Kn];  // 9216 B
    for (int i = threadIdx.x; i < Kn * Kn; i += 128) s_tr[i] = trans[i];
    __syncthreads();

    const int seq  = blockIdx.x * 4 + (threadIdx.x >> 5);
    const int lane = threadIdx.x & 31;
    const bool has2 = (lane < Kn - 32);   // second candidate p = lane + 32

    const float* fvb = g_fv + (size_t)seq * Tn * Kn;
    float* op = out + Bn + (size_t)seq * Tn;
    int tag = g_btag[seq];

    // depth-PD register pipeline of fv rows (guaranteed loads, not hints)
    float va[PD], vb[PD];
#pragma unroll
    for (int d = 0; d < PD; ++d) {
        const float* row = fvb + (size_t)(Tn - 1 - d) * Kn;
        va[d] = __ldg(row + lane);
        vb[d] = has2 ? __ldg(row + 32 + lane) : 0.0f;
    }

    float path_val = 0.0f;
    int t = Tn - 1;
    for (int iter = 0; iter < Tn / PD; ++iter) {
#pragma unroll
        for (int u = 0; u < PD; ++u) {
            if (lane == (t & 31)) path_val = (float)tag;  // path[t] = entry tag

            // bptr[t][tag] = first-index argmax_p( fv_t[p] + trans[tag][p] )
            const float* trow = s_tr + tag * Kn;
            unsigned o1 = ordered_u32(va[u] + trow[lane]);
            unsigned o2 = 0;  // safe floor sentinel for lanes without p2
            if (has2) o2 = ordered_u32(vb[u] + trow[32 + lane]);

            unsigned m = (o1 > o2) ? o1 : o2;
            unsigned omax = __reduce_max_sync(0xffffffffu, m);
            unsigned b1 = __ballot_sync(0xffffffffu, o1 == omax);
            unsigned b2 = __ballot_sync(0xffffffffu, o2 == omax);
            tag = b1 ? (__ffs(b1) - 1) : (31 + __ffs(b2));

            // refill pipeline slot with row t-PD
            const int tl = t - PD;
            if (tl >= 0) {
                const float* row = fvb + (size_t)tl * Kn;
                va[u] = __ldg(row + lane);
                vb[u] = has2 ? __ldg(row + 32 + lane) : 0.0f;
            }

            // coalesced flush every 32 steps
            if ((t & 31) == 0) op[t + lane] = path_val;
            --t;
        }
    }
}

extern "C" void kernel_launch(void* const* d_in, const int* in_sizes, int n_in,
                              void* d_out, int out_size) {
    (void)n_in; (void)out_size;
    const float* feats = (const float*)d_in[0];
    const float* trans = (const float*)d_in[1];
    if (in_sizes[0] == Kn * Kn && in_sizes[1] != Kn * Kn) {
        const float* tmp = feats; feats = trans; trans = tmp;
    }
    float* out = (float*)d_out;

    viterbi_fwd<<<Bn / SUBS, NTHREADS>>>(feats, trans, out);
    viterbi_path<<<Bn / 4, 128>>>(trans, out);
}

// round 17
// speedup vs baseline: 1.6463x; 1.3168x over previous
#include <cuda_runtime.h>

// Batched Viterbi decode: B=1024 sequences, T=1024 steps, K=48 tags.
// Output layout (float32): [0, B) = path scores, [B, B + B*T) = best paths.
//
// R15: forward parallelism doubled — 2 threads per next-tag (96 threads per
// sequence, 1024 blocks -> 3072 warps = 21/SM vs 10). Each thread reduces 24
// prev-candidates (12 packed f32x2 adds + fmax tree), halves merged with one
// shfl.bfly. fmax is exactly associative -> bit-identical values. Path-chase
// kernel unchanged from R13 (proven).

namespace {
constexpr int Bn = 1024;
constexpr int Tn = 1024;
constexpr int Kn = 48;
constexpr int START_TAG = 46;
constexpr float NEGV = -10000.0f;

constexpr int NTHREADS = 2 * Kn;     // 96: 2 threads per next-tag
constexpr int PD = 8;                // path-kernel row pipeline depth
}

// Scratch (__device__ globals: allowed; no allocation APIs).
__device__ __align__(16) float g_fv[(size_t)Bn * Tn * Kn];  // 192 MB fv rows
__device__ int g_btag[Bn];                                   // terminal best tag

// packed f32x2 add: two independent IEEE-rn adds in one instruction
__device__ __forceinline__ void fadd2(unsigned long long a, unsigned long long b,
                                      float& lo, float& hi) {
    unsigned long long s;
    asm("add.rn.f32x2 %0, %1, %2;" : "=l"(s) : "l"(a), "l"(b));
    asm("mov.b64 {%0, %1}, %2;" : "=f"(lo), "=f"(hi) : "l"(s));
}

// monotone bijection float -> u32 (order-preserving for all non-NaN floats)
__device__ __forceinline__ unsigned ordered_u32(float x) {
    int b = __float_as_int(x);
    return (unsigned)(b ^ ((b >> 31) | 0x80000000));
}

__global__ __launch_bounds__(NTHREADS) void viterbi_fwd(
    const float* __restrict__ feats,   // [B, T, K]
    const float* __restrict__ trans,   // [K, K]  trans[next][prev]
    float* __restrict__ out)           // [B] scores
{
    __shared__ __align__(16) float fvbuf[2][Kn];

    const int u = threadIdx.x;
    const int j = u >> 1;              // next-tag owned by this pair
    const int h = u & 1;               // which half of the prev-dimension
    const int b = blockIdx.x;

    // My 24 transition entries trans[j][h*24 .. h*24+23], packed f32x2.
    unsigned long long tr2[12];
#pragma unroll
    for (int p = 0; p < 24; p += 2) {
        const int base = j * Kn + h * 24 + p;
        unsigned long long lo = __float_as_uint(trans[base]);
        unsigned long long hi = __float_as_uint(trans[base + 1]);
        tr2[p / 2] = lo | (hi << 32);
    }

    float* fvout = g_fv + (size_t)b * Tn * Kn;  // rows: fv entering step t
    if (h == 0) {
        const float init = (j == START_TAG) ? 0.0f : NEGV;
        fvbuf[0][j] = init;
        fvout[j] = init;                         // row 0
    }
    __syncthreads();

    const float* fb = feats + (size_t)b * Tn * Kn;

    // depth-2 register pipeline for the emission loads (pair shares address)
    float f0 = __ldg(fb + j);
    float f1 = __ldg(fb + Kn + j);

    for (int t = 0; t < Tn; ++t) {
        const int rbuf = t & 1;
        const float feat = f0;
        f0 = f1;
        const int tn = (t + 2 < Tn) ? (t + 2) : (Tn - 1);
        f1 = __ldg(fb + (size_t)tn * Kn + j);

        // my 24 fv values as packed pairs (6x LDS.128, broadcast-friendly)
        const ulonglong2* fvv =
            reinterpret_cast<const ulonglong2*>(&fvbuf[rbuf][h * 24]);
        unsigned long long fvp[12];
#pragma unroll
        for (int i = 0; i < 6; ++i) {
            ulonglong2 v = fvv[i];
            fvp[2 * i] = v.x; fvp[2 * i + 1] = v.y;
        }

        // 24 sums -> balanced fmax tree (exact: fmax associative)
        float m12[12];
#pragma unroll
        for (int g = 0; g < 6; ++g) {
            float x0, x1, x2, x3;
            fadd2(fvp[2 * g],     tr2[2 * g],     x0, x1);
            fadd2(fvp[2 * g + 1], tr2[2 * g + 1], x2, x3);
            m12[2 * g]     = fmaxf(x0, x1);
            m12[2 * g + 1] = fmaxf(x2, x3);
        }
        float m6[6];
#pragma unroll
        for (int i = 0; i < 6; ++i) m6[i] = fmaxf(m12[2 * i], m12[2 * i + 1]);
        float m3a = fmaxf(m6[0], m6[1]);
        float m3b = fmaxf(m6[2], m6[3]);
        float m3c = fmaxf(m6[4], m6[5]);
        const float part = fmaxf(fmaxf(m3a, m3b), m3c);   // max of my 24

        // merge the two halves of the pair
        const float other = __shfl_xor_sync(0xffffffffu, part, 1);
        const float nv = fmaxf(part, other) + feat;

        if (h == 0) {
            if (t + 1 < Tn) fvout[(size_t)(t + 1) * Kn + j] = nv;
            fvbuf[rbuf ^ 1][j] = nv;
        }
        __syncthreads();
    }

    // terminal: strict-> ascending scan reproduces jnp.argmax first-index
    if (u == 0) {
        const float* fvf = &fvbuf[0][0];   // t=1023 wrote buffer 0
        const float* trow = trans + (Kn - 1) * Kn;
        float bestv = fvf[0] + __ldg(trow);
        int best = 0;
#pragma unroll
        for (int k = 1; k < Kn; ++k) {
            float s = fvf[k] + __ldg(trow + k);
            if (s > bestv) { bestv = s; best = k; }
        }
        out[b] = bestv;
        g_btag[b] = best;
    }
}

// ---- Path chase: one warp per sequence; fv rows in a register pipeline ----
__global__ __launch_bounds__(128) void viterbi_path(
    const float* __restrict__ trans,
    float* __restrict__ out)
{
    __shared__ float s_tr[Kn * Kn];  // 9216 B
    for (int i = threadIdx.x; i < Kn * Kn; i += 128) s_tr[i] = trans[i];
    __syncthreads();

    const int seq  = blockIdx.x * 4 + (threadIdx.x >> 5);
    const int lane = threadIdx.x & 31;
    const bool has2 = (lane < Kn - 32);   // second candidate p = lane + 32

    const float* fvb = g_fv + (size_t)seq * Tn * Kn;
    float* op = out + Bn + (size_t)seq * Tn;
    int tag = g_btag[seq];

    // depth-PD register pipeline of fv rows (guaranteed loads, not hints)
    float va[PD], vb[PD];
#pragma unroll
    for (int d = 0; d < PD; ++d) {
        const float* row = fvb + (size_t)(Tn - 1 - d) * Kn;
        va[d] = __ldg(row + lane);
        vb[d] = has2 ? __ldg(row + 32 + lane) : 0.0f;
    }

    float path_val = 0.0f;
    int t = Tn - 1;
    for (int iter = 0; iter < Tn / PD; ++iter) {
#pragma unroll
        for (int u = 0; u < PD; ++u) {
            if (lane == (t & 31)) path_val = (float)tag;  // path[t] = entry tag

            // bptr[t][tag] = first-index argmax_p( fv_t[p] + trans[tag][p] )
            const float* trow = s_tr + tag * Kn;
            unsigned o1 = ordered_u32(va[u] + trow[lane]);
            unsigned o2 = 0;  // safe floor sentinel for lanes without p2
            if (has2) o2 = ordered_u32(vb[u] + trow[32 + lane]);

            unsigned m = (o1 > o2) ? o1 : o2;
            unsigned omax = __reduce_max_sync(0xffffffffu, m);
            unsigned b1 = __ballot_sync(0xffffffffu, o1 == omax);
            unsigned b2 = __ballot_sync(0xffffffffu, o2 == omax);
            tag = b1 ? (__ffs(b1) - 1) : (31 + __ffs(b2));

            // refill pipeline slot with row t-PD
            const int tl = t - PD;
            if (tl >= 0) {
                const float* row = fvb + (size_t)tl * Kn;
                va[u] = __ldg(row + lane);
                vb[u] = has2 ? __ldg(row + 32 + lane) : 0.0f;
            }

            // coalesced flush every 32 steps
            if ((t & 31) == 0) op[t + lane] = path_val;
            --t;
        }
    }
}

extern "C" void kernel_launch(void* const* d_in, const int* in_sizes, int n_in,
                              void* d_out, int out_size) {
    (void)n_in; (void)out_size;
    const float* feats = (const float*)d_in[0];
    const float* trans = (const float*)d_in[1];
    if (in_sizes[0] == Kn * Kn && in_sizes[1] != Kn * Kn) {
        const float* tmp = feats; feats = trans; trans = tmp;
    }
    float* out = (float*)d_out;

    viterbi_fwd<<<Bn, NTHREADS>>>(feats, trans, out);
    viterbi_path<<<Bn / 4, 128>>>(trans, out);
}